// round 5
// baseline (speedup 1.0000x reference)
#include <cuda_runtime.h>
#include <cstdint>

#define GG 512            // B*T graphs
#define NN 500            // nodes
#define FIN 96
#define HID 64
#define OUTF 96
#define ROWS (GG*NN)      // 256000
#define BN_EPS 1e-5f
#define NNZ_MAX (NN*NN)

// ---------------- scratch (device globals; no allocation allowed) ----------------
__device__ float g_t[(long)ROWS*HID];    // GEMM output / SpMM input
__device__ float g_s[(long)ROWS*HID];    // SpMM output
__device__ float g_h[(long)ROWS*HID];    // layer activations (residual chain)
__device__ float g_r[(long)ROWS*HID];    // layer-0 residual (x @ w_r0 + b_r0)
__device__ float g_dinv[NN];
__device__ int   g_cnt[NN];
__device__ int   g_rowptr[NN+1];
__device__ float2 g_ecsr[NNZ_MAX];       // packed (col-as-int-bits, val)
__device__ float g_sum[HID];
__device__ float g_sumsq[HID];
__device__ float g_scale[HID];
__device__ float g_shift[HID];

// ---------------- prep: degrees / dinv + per-row nnz counts ----------------
__global__ void prep_deg(const float* __restrict__ adj) {
    int m = blockIdx.x;
    int tid = threadIdx.x;
    float sum = 0.f; int cnt = 0;
    for (int n = tid; n < NN; n += blockDim.x) {
        float a = adj[m*NN + n];
        sum += a;
        cnt += (a != 0.f) ? 1 : 0;
    }
    __shared__ float ssum[4]; __shared__ int scnt[4];
    #pragma unroll
    for (int o = 16; o; o >>= 1) {
        sum += __shfl_down_sync(0xFFFFFFFFu, sum, o);
        cnt += __shfl_down_sync(0xFFFFFFFFu, cnt, o);
    }
    int w = tid >> 5;
    if ((tid & 31) == 0) { ssum[w] = sum; scnt[w] = cnt; }
    __syncthreads();
    if (tid == 0) {
        float s = ssum[0] + ssum[1] + ssum[2] + ssum[3];
        int c = scnt[0] + scnt[1] + scnt[2] + scnt[3];
        g_dinv[m] = rsqrtf(1.f + s);
        g_cnt[m] = c + 1;   // + diagonal
    }
    if (blockIdx.x == 0 && tid < HID) { g_sum[tid] = 0.f; g_sumsq[tid] = 0.f; }
}

// exclusive scan of row counts -> rowptr (single block)
__global__ void prep_scan() {
    __shared__ int sc[512];
    int tid = threadIdx.x;
    sc[tid] = (tid < NN) ? g_cnt[tid] : 0;
    __syncthreads();
    for (int off = 1; off < 512; off <<= 1) {
        int v = (tid >= off) ? sc[tid - off] : 0;
        __syncthreads();
        sc[tid] += v;
        __syncthreads();
    }
    if (tid < NN) g_rowptr[tid + 1] = sc[tid];
    if (tid == 0) g_rowptr[0] = 0;
}

// fill CSR with normalized values (deterministic: one thread per row, ascending cols)
__global__ void prep_fill(const float* __restrict__ adj) {
    int m = blockIdx.x * blockDim.x + threadIdx.x;
    if (m >= NN) return;
    float dm = g_dinv[m];
    int p = g_rowptr[m];
    for (int n = 0; n < NN; n++) {
        if (n == m) {
            g_ecsr[p] = make_float2(__int_as_float(m), dm * dm);
            p++;
        } else {
            float a = adj[m*NN + n];
            if (a != 0.f) {
                g_ecsr[p] = make_float2(__int_as_float(n), dm * a * g_dinv[n]);
                p++;
            }
        }
    }
}

// ---------------- tensor-core GEMM (3xTF32 split, fp32-equivalent accuracy) -------
// C[row,c] = sum_f A'[row,f]*B[f,c] + bias[c]   (optional += existing C)
// FUSE: A'[row,f] = max(A[row,f]*scale[f]+shift[f], 0) + R[row,f]  (BN+ReLU+residual)
//       optionally written out to Hout.
__device__ __forceinline__ void tf32_split(float x, uint32_t& hi, uint32_t& lo) {
    asm("cvt.rna.tf32.f32 %0, %1;" : "=r"(hi) : "f"(x));
    float r = x - __uint_as_float(hi);
    asm("cvt.rna.tf32.f32 %0, %1;" : "=r"(lo) : "f"(r));
}

__device__ __forceinline__ void mma_tf32(float* c, const uint32_t* a, const uint32_t* b) {
    asm volatile(
        "mma.sync.aligned.m16n8k8.row.col.f32.tf32.tf32.f32 "
        "{%0,%1,%2,%3}, {%4,%5,%6,%7}, {%8,%9}, {%0,%1,%2,%3};\n"
        : "+f"(c[0]), "+f"(c[1]), "+f"(c[2]), "+f"(c[3])
        : "r"(a[0]), "r"(a[1]), "r"(a[2]), "r"(a[3]), "r"(b[0]), "r"(b[1]));
}

template<int K, int C, bool ACCUM, bool FUSE, bool WRITE_H>
__global__ __launch_bounds__(256) void gemm_tc(
    const float* __restrict__ A, const float* __restrict__ R, float* __restrict__ Hout,
    const float* __restrict__ Bw, const float* __restrict__ bias, float* __restrict__ Cout)
{
    __shared__ float As[128][36];
    __shared__ float Bs[32][68];
    __shared__ float s_scale[HID], s_shift[HID];

    const int tid = threadIdx.x;
    const int wid = tid >> 5;
    const int lane = tid & 31;
    const int g  = lane >> 2;
    const int t4 = lane & 3;
    const int warp_m = wid >> 1;
    const int warp_n = wid & 1;

    const long row0 = (long)blockIdx.x * 128;
    const int col0 = blockIdx.y * 64;

    if (FUSE) {
        if (tid < HID) s_scale[tid] = g_scale[tid];
        else if (tid < 2*HID) s_shift[tid - HID] = g_shift[tid - HID];
        __syncthreads();
    }

    float acc[2][4][4];
    #pragma unroll
    for (int mt = 0; mt < 2; mt++)
        #pragma unroll
        for (int nt = 0; nt < 4; nt++)
            #pragma unroll
            for (int q = 0; q < 4; q++) acc[mt][nt][q] = 0.f;

    for (int k0 = 0; k0 < K; k0 += 32) {
        #pragma unroll
        for (int i = 0; i < 4; i++) {
            int idx = tid + i * 256;
            int r = idx >> 3;
            int q = idx & 7;
            long off = (row0 + r) * K + (k0 + q * 4);
            float4 v = *(const float4*)(A + off);
            if (FUSE) {
                int kc = k0 + q * 4;
                float4 rv = *(const float4*)(R + off);
                v.x = fmaxf(v.x * s_scale[kc+0] + s_shift[kc+0], 0.f) + rv.x;
                v.y = fmaxf(v.y * s_scale[kc+1] + s_shift[kc+1], 0.f) + rv.y;
                v.z = fmaxf(v.z * s_scale[kc+2] + s_shift[kc+2], 0.f) + rv.z;
                v.w = fmaxf(v.w * s_scale[kc+3] + s_shift[kc+3], 0.f) + rv.w;
                if (WRITE_H) *(float4*)(Hout + off) = v;
            }
            As[r][q*4+0] = v.x; As[r][q*4+1] = v.y;
            As[r][q*4+2] = v.z; As[r][q*4+3] = v.w;
        }
        #pragma unroll
        for (int i = 0; i < 2; i++) {
            int idx = tid + i * 256;
            int kk = idx >> 4;
            int q = idx & 15;
            int c = col0 + q * 4;
            float4 v = make_float4(0.f, 0.f, 0.f, 0.f);
            if ((C & 63) == 0 || c < C)
                v = *(const float4*)(Bw + (k0 + kk) * C + c);
            *(float4*)&Bs[kk][q*4] = v;
        }
        __syncthreads();

        #pragma unroll
        for (int kk = 0; kk < 4; kk++) {
            uint32_t ahi[2][4], alo[2][4];
            #pragma unroll
            for (int mt = 0; mt < 2; mt++) {
                int r = warp_m * 32 + mt * 16 + g;
                int kc = kk * 8 + t4;
                tf32_split(As[r][kc],        ahi[mt][0], alo[mt][0]);
                tf32_split(As[r + 8][kc],    ahi[mt][1], alo[mt][1]);
                tf32_split(As[r][kc + 4],    ahi[mt][2], alo[mt][2]);
                tf32_split(As[r + 8][kc + 4],ahi[mt][3], alo[mt][3]);
            }
            uint32_t bhi[4][2], blo[4][2];
            #pragma unroll
            for (int nt = 0; nt < 4; nt++) {
                int nb = warp_n * 32 + nt * 8 + g;
                int kr = kk * 8 + t4;
                tf32_split(Bs[kr][nb],     bhi[nt][0], blo[nt][0]);
                tf32_split(Bs[kr + 4][nb], bhi[nt][1], blo[nt][1]);
            }
            #pragma unroll
            for (int mt = 0; mt < 2; mt++)
                #pragma unroll
                for (int nt = 0; nt < 4; nt++) {
                    mma_tf32(acc[mt][nt], ahi[mt], bhi[nt]);
                    mma_tf32(acc[mt][nt], ahi[mt], blo[nt]);
                    mma_tf32(acc[mt][nt], alo[mt], bhi[nt]);
                }
        }
        __syncthreads();
    }

    #pragma unroll
    for (int mt = 0; mt < 2; mt++) {
        long rowa = row0 + warp_m * 32 + mt * 16 + g;
        long rowb = rowa + 8;
        #pragma unroll
        for (int nt = 0; nt < 4; nt++) {
            int col = col0 + warp_n * 32 + nt * 8 + 2 * t4;
            if ((C & 63) == 0 || col < C) {
                float bx = bias[col];
                float by = bias[col + 1];
                float* d0 = Cout + rowa * C + col;
                float* d1 = Cout + rowb * C + col;
                float2 v0 = make_float2(acc[mt][nt][0] + bx, acc[mt][nt][1] + by);
                float2 v1 = make_float2(acc[mt][nt][2] + bx, acc[mt][nt][3] + by);
                if (ACCUM) {
                    float2 o0 = *(const float2*)d0;
                    float2 o1 = *(const float2*)d1;
                    v0.x += o0.x; v0.y += o0.y;
                    v1.x += o1.x; v1.y += o1.y;
                }
                *(float2*)d0 = v0;
                *(float2*)d1 = v1;
            }
        }
    }
}

// ---------------- SpMM via smem-staged gather + BN stats ----------------
// grid = (GG, 2): one graph x one 32-channel half per block; 256 threads = 8 warps.
// Stage T[g][:, half] (500 x 32ch = 64000 B) in dynamic smem; warp per row,
// 32 lanes = 4 nnz-slots x 8 float4-channel-lanes; gather from LDS (no L1tex
// wavefront replays), reduce slots via shfl, coalesced stores + block BN stats.
__global__ __launch_bounds__(256) void spmm_stats_smem(
    const float* __restrict__ T, float* __restrict__ S)
{
    extern __shared__ float4 sT[];            // [NN*8] float4 = 64000 B
    __shared__ float4 red_s[8][8], red_q[8][8];

    const int g = blockIdx.x;
    const int h = blockIdx.y;                 // channel half: 0 or 1
    const int tid = threadIdx.x;
    const int wid = tid >> 5;
    const int lane = tid & 31;
    const int slot = lane >> 3;               // 0..3 (nnz slot)
    const int chl = lane & 7;                 // 0..7 (float4 channel lane)

    const float4* tg4 = (const float4*)(T + (long)g * NN * HID);
    float4* sg4 = (float4*)(S + (long)g * NN * HID);

    // stage the half-tile (coalesced)
    for (int idx = tid; idx < NN * 8; idx += 256) {
        int r = idx >> 3, q = idx & 7;
        sT[idx] = tg4[r * 16 + h * 8 + q];
    }
    __syncthreads();

    float4 lsum = make_float4(0.f, 0.f, 0.f, 0.f);
    float4 lsq  = make_float4(0.f, 0.f, 0.f, 0.f);

    for (int m = wid; m < NN; m += 8) {
        int jb = g_rowptr[m], je = g_rowptr[m + 1];
        float4 acc = make_float4(0.f, 0.f, 0.f, 0.f);
        for (int j = jb + slot; j < je; j += 4) {
            float2 cv = g_ecsr[j];
            int col = __float_as_int(cv.x);
            float w = cv.y;
            float4 t = sT[col * 8 + chl];
            acc.x += w * t.x; acc.y += w * t.y;
            acc.z += w * t.z; acc.w += w * t.w;
        }
        // reduce across the 4 nnz slots (lane strides 16 then 8)
        acc.x += __shfl_down_sync(0xFFFFFFFFu, acc.x, 16);
        acc.y += __shfl_down_sync(0xFFFFFFFFu, acc.y, 16);
        acc.z += __shfl_down_sync(0xFFFFFFFFu, acc.z, 16);
        acc.w += __shfl_down_sync(0xFFFFFFFFu, acc.w, 16);
        acc.x += __shfl_down_sync(0xFFFFFFFFu, acc.x, 8);
        acc.y += __shfl_down_sync(0xFFFFFFFFu, acc.y, 8);
        acc.z += __shfl_down_sync(0xFFFFFFFFu, acc.z, 8);
        acc.w += __shfl_down_sync(0xFFFFFFFFu, acc.w, 8);
        if (slot == 0) {
            sg4[m * 16 + h * 8 + chl] = acc;
            lsum.x += acc.x; lsum.y += acc.y; lsum.z += acc.z; lsum.w += acc.w;
            lsq.x += acc.x * acc.x; lsq.y += acc.y * acc.y;
            lsq.z += acc.z * acc.z; lsq.w += acc.w * acc.w;
        }
    }

    if (slot == 0) { red_s[wid][chl] = lsum; red_q[wid][chl] = lsq; }
    __syncthreads();
    if (tid < 8) {
        float4 s = red_s[0][tid], q = red_q[0][tid];
        #pragma unroll
        for (int w = 1; w < 8; w++) {
            float4 a = red_s[w][tid], b = red_q[w][tid];
            s.x += a.x; s.y += a.y; s.z += a.z; s.w += a.w;
            q.x += b.x; q.y += b.y; q.z += b.z; q.w += b.w;
        }
        int c = h * 32 + tid * 4;
        atomicAdd(&g_sum[c+0], s.x); atomicAdd(&g_sum[c+1], s.y);
        atomicAdd(&g_sum[c+2], s.z); atomicAdd(&g_sum[c+3], s.w);
        atomicAdd(&g_sumsq[c+0], q.x); atomicAdd(&g_sumsq[c+1], q.y);
        atomicAdd(&g_sumsq[c+2], q.z); atomicAdd(&g_sumsq[c+3], q.w);
    }
}

// ---------------- BN finalize ----------------
__global__ void bn_finalize(const float* __restrict__ gamma, const float* __restrict__ beta) {
    int c = threadIdx.x;
    float s = g_sum[c], q = g_sumsq[c];
    const float inv = 1.f / (float)ROWS;
    float mean = s * inv;
    float var = q * inv - mean * mean;
    float rstd = rsqrtf(var + BN_EPS);
    float a = rstd * gamma[c];
    g_scale[c] = a;
    g_shift[c] = beta[c] - mean * a;
    g_sum[c] = 0.f; g_sumsq[c] = 0.f;
}

// ---------------- launch ----------------
extern "C" void kernel_launch(void* const* d_in, const int* in_sizes, int n_in,
                              void* d_out, int out_size)
{
    const float* x     = (const float*)d_in[0];
    const float* adj   = (const float*)d_in[1];
    const float* w_g0  = (const float*)d_in[2];
    const float* b_g0  = (const float*)d_in[3];
    const float* w_g1  = (const float*)d_in[4];
    const float* b_g1  = (const float*)d_in[5];
    const float* w_g2  = (const float*)d_in[6];
    const float* b_g2  = (const float*)d_in[7];
    const float* gamma = (const float*)d_in[8];
    const float* beta  = (const float*)d_in[9];
    const float* w_r0  = (const float*)d_in[10];
    const float* b_r0  = (const float*)d_in[11];
    const float* w_fc  = (const float*)d_in[12];
    const float* b_fc  = (const float*)d_in[13];
    const float* w_fr  = (const float*)d_in[14];
    const float* b_fr  = (const float*)d_in[15];
    float* out = (float*)d_out;

    float *pt, *ps, *ph, *pr;
    cudaGetSymbolAddress((void**)&pt, g_t);
    cudaGetSymbolAddress((void**)&ps, g_s);
    cudaGetSymbolAddress((void**)&ph, g_h);
    cudaGetSymbolAddress((void**)&pr, g_r);

    const int ROWB = ROWS / 128;               // 2000
    const int SPMM_SMEM = NN * 8 * 16;         // 64000 B

    cudaFuncSetAttribute(spmm_stats_smem,
                         cudaFuncAttributeMaxDynamicSharedMemorySize, SPMM_SMEM);

    // CSR of a_hat (recomputed every launch; tiny, fully deterministic)
    prep_deg<<<NN, 128>>>(adj);
    prep_scan<<<1, 512>>>();
    prep_fill<<<4, 128>>>(adj);

    // input GEMMs: t0 = x@w_g0+b, r0 = x@w_r0+b, out = x@w_fr+b_fr
    gemm_tc<FIN, HID, false, false, false><<<dim3(ROWB, 1), 256>>>(x, nullptr, nullptr, w_g0, b_g0, pt);
    gemm_tc<FIN, HID, false, false, false><<<dim3(ROWB, 1), 256>>>(x, nullptr, nullptr, w_r0, b_r0, pr);
    gemm_tc<FIN, OUTF, false, false, false><<<dim3(ROWB, 2), 256>>>(x, nullptr, nullptr, w_fr, b_fr, out);

    // layer 0: s = a_hat @ t0; h0 = relu(bn(s)) + r0; t1 = h0 @ w_g1 + b
    spmm_stats_smem<<<dim3(GG, 2), 256, SPMM_SMEM>>>(pt, ps);
    bn_finalize<<<1, HID>>>(gamma + 0 * HID, beta + 0 * HID);
    gemm_tc<HID, HID, false, true, true><<<dim3(ROWB, 1), 256>>>(ps, pr, ph, w_g1, b_g1, pt);

    // layer 1: s = a_hat @ t1; h1 = relu(bn(s)) + h0; t2 = h1 @ w_g2 + b
    spmm_stats_smem<<<dim3(GG, 2), 256, SPMM_SMEM>>>(pt, ps);
    bn_finalize<<<1, HID>>>(gamma + 1 * HID, beta + 1 * HID);
    gemm_tc<HID, HID, false, true, true><<<dim3(ROWB, 1), 256>>>(ps, ph, ph, w_g2, b_g2, pt);

    // layer 2: s = a_hat @ t2; h2 = relu(bn(s)) + h1 (never materialized);
    //          out += h2 @ w_fc + b_fc
    spmm_stats_smem<<<dim3(GG, 2), 256, SPMM_SMEM>>>(pt, ps);
    bn_finalize<<<1, HID>>>(gamma + 2 * HID, beta + 2 * HID);
    gemm_tc<HID, OUTF, true, true, false><<<dim3(ROWB, 2), 256>>>(ps, ph, nullptr, w_fc, b_fc, out);
}

// round 6
// speedup vs baseline: 1.1404x; 1.1404x over previous
#include <cuda_runtime.h>
#include <cstdint>

#define GG 512            // B*T graphs
#define NN 500            // nodes
#define FIN 96
#define HID 64
#define OUTF 96
#define ROWS (GG*NN)      // 256000
#define BN_EPS 1e-5f
#define NNZ_MAX (NN*NN)

// ---------------- scratch (device globals; no allocation allowed) ----------------
__device__ float g_t[(long)ROWS*HID];    // GEMM output / SpMM input
__device__ float g_s[(long)ROWS*HID];    // SpMM output
__device__ float g_h[(long)ROWS*HID];    // layer activations (residual chain)
__device__ float g_r[(long)ROWS*HID];    // layer-0 residual (x @ w_r0 + b_r0)
__device__ float g_dinv[NN];
__device__ int   g_cnt[NN];
__device__ int   g_rowptr[NN+1];
__device__ float2 g_ecsr[NNZ_MAX];       // packed (col-as-int-bits, val)
__device__ float g_sum[HID];
__device__ float g_sumsq[HID];
__device__ float g_scale[HID];
__device__ float g_shift[HID];

// ---------------- prep: degrees / dinv + per-row nnz counts ----------------
__global__ void prep_deg(const float* __restrict__ adj) {
    int m = blockIdx.x;
    int tid = threadIdx.x;
    float sum = 0.f; int cnt = 0;
    for (int n = tid; n < NN; n += blockDim.x) {
        float a = adj[m*NN + n];
        sum += a;
        cnt += (a != 0.f) ? 1 : 0;
    }
    __shared__ float ssum[4]; __shared__ int scnt[4];
    #pragma unroll
    for (int o = 16; o; o >>= 1) {
        sum += __shfl_down_sync(0xFFFFFFFFu, sum, o);
        cnt += __shfl_down_sync(0xFFFFFFFFu, cnt, o);
    }
    int w = tid >> 5;
    if ((tid & 31) == 0) { ssum[w] = sum; scnt[w] = cnt; }
    __syncthreads();
    if (tid == 0) {
        float s = ssum[0] + ssum[1] + ssum[2] + ssum[3];
        int c = scnt[0] + scnt[1] + scnt[2] + scnt[3];
        g_dinv[m] = rsqrtf(1.f + s);
        g_cnt[m] = c + 1;   // + diagonal
    }
    if (blockIdx.x == 0 && tid < HID) { g_sum[tid] = 0.f; g_sumsq[tid] = 0.f; }
}

// exclusive scan of row counts -> rowptr (single block)
__global__ void prep_scan() {
    __shared__ int sc[512];
    int tid = threadIdx.x;
    sc[tid] = (tid < NN) ? g_cnt[tid] : 0;
    __syncthreads();
    for (int off = 1; off < 512; off <<= 1) {
        int v = (tid >= off) ? sc[tid - off] : 0;
        __syncthreads();
        sc[tid] += v;
        __syncthreads();
    }
    if (tid < NN) g_rowptr[tid + 1] = sc[tid];
    if (tid == 0) g_rowptr[0] = 0;
}

// fill CSR with normalized values (deterministic: one thread per row, ascending cols)
__global__ void prep_fill(const float* __restrict__ adj) {
    int m = blockIdx.x * blockDim.x + threadIdx.x;
    if (m >= NN) return;
    float dm = g_dinv[m];
    int p = g_rowptr[m];
    for (int n = 0; n < NN; n++) {
        if (n == m) {
            g_ecsr[p] = make_float2(__int_as_float(m), dm * dm);
            p++;
        } else {
            float a = adj[m*NN + n];
            if (a != 0.f) {
                g_ecsr[p] = make_float2(__int_as_float(n), dm * a * g_dinv[n]);
                p++;
            }
        }
    }
}

// ---------------- tensor-core GEMM (3xTF32 split, fp32-equivalent accuracy) -------
// C[row,c] = sum_f A'[row,f]*B[f,c] + bias[c]   (optional += existing C)
// FUSE: A'[row,f] = max(A[row,f]*scale[f]+shift[f], 0) + R[row,f]  (BN+ReLU+residual)
//       optionally written out to Hout.
// hi/lo tf32 planes are PRE-SPLIT into smem at tile-load time; the k-loop is
// pure conflict-free LDS + MMA.

__device__ __forceinline__ void tf32_split(float x, uint32_t& hi, uint32_t& lo) {
    asm("cvt.rna.tf32.f32 %0, %1;" : "=r"(hi) : "f"(x));
    float r = x - __uint_as_float(hi);
    asm("cvt.rna.tf32.f32 %0, %1;" : "=r"(lo) : "f"(r));
}

__device__ __forceinline__ void mma_tf32(float* c, const uint32_t* a, const uint32_t* b) {
    asm volatile(
        "mma.sync.aligned.m16n8k8.row.col.f32.tf32.tf32.f32 "
        "{%0,%1,%2,%3}, {%4,%5,%6,%7}, {%8,%9}, {%0,%1,%2,%3};\n"
        : "+f"(c[0]), "+f"(c[1]), "+f"(c[2]), "+f"(c[3])
        : "r"(a[0]), "r"(a[1]), "r"(a[2]), "r"(a[3]), "r"(b[0]), "r"(b[1]));
}

// dynamic smem layout (uint32 words):
//   AsH [128][36]  : 4608 words
//   AsL [128][36]  : 4608
//   BsH [32][72]   : 2304   (stride 72 -> frag banks 8*t4+g = 0..31, conflict-free)
//   BsL [32][72]   : 2304
#define GEMM_SMEM_WORDS (4608*2 + 2304*2)
#define GEMM_SMEM_BYTES (GEMM_SMEM_WORDS * 4)

template<int K, int C, bool ACCUM, bool FUSE, bool WRITE_H>
__global__ __launch_bounds__(256) void gemm_tc(
    const float* __restrict__ A, const float* __restrict__ R, float* __restrict__ Hout,
    const float* __restrict__ Bw, const float* __restrict__ bias, float* __restrict__ Cout)
{
    extern __shared__ uint32_t dsm[];
    uint32_t (*AsH)[36] = (uint32_t(*)[36])(dsm);
    uint32_t (*AsL)[36] = (uint32_t(*)[36])(dsm + 4608);
    uint32_t (*BsH)[72] = (uint32_t(*)[72])(dsm + 9216);
    uint32_t (*BsL)[72] = (uint32_t(*)[72])(dsm + 11520);
    __shared__ float s_scale[HID], s_shift[HID];

    const int tid = threadIdx.x;
    const int wid = tid >> 5;
    const int lane = tid & 31;
    const int g  = lane >> 2;
    const int t4 = lane & 3;
    const int warp_m = wid >> 1;
    const int warp_n = wid & 1;

    const long row0 = (long)blockIdx.x * 128;
    const int col0 = blockIdx.y * 64;

    if (FUSE) {
        if (tid < HID) s_scale[tid] = g_scale[tid];
        else if (tid < 2*HID) s_shift[tid - HID] = g_shift[tid - HID];
        __syncthreads();
    }

    float acc[2][4][4];
    #pragma unroll
    for (int mt = 0; mt < 2; mt++)
        #pragma unroll
        for (int nt = 0; nt < 4; nt++)
            #pragma unroll
            for (int q = 0; q < 4; q++) acc[mt][nt][q] = 0.f;

    for (int k0 = 0; k0 < K; k0 += 32) {
        // --- load + pre-split A tile: 128 rows x 32 k ---
        #pragma unroll
        for (int i = 0; i < 4; i++) {
            int idx = tid + i * 256;
            int r = idx >> 3;
            int q = idx & 7;
            long off = (row0 + r) * K + (k0 + q * 4);
            float4 v = *(const float4*)(A + off);
            if (FUSE) {
                int kc = k0 + q * 4;
                float4 rv = *(const float4*)(R + off);
                v.x = fmaxf(v.x * s_scale[kc+0] + s_shift[kc+0], 0.f) + rv.x;
                v.y = fmaxf(v.y * s_scale[kc+1] + s_shift[kc+1], 0.f) + rv.y;
                v.z = fmaxf(v.z * s_scale[kc+2] + s_shift[kc+2], 0.f) + rv.z;
                v.w = fmaxf(v.w * s_scale[kc+3] + s_shift[kc+3], 0.f) + rv.w;
                if (WRITE_H) *(float4*)(Hout + off) = v;
            }
            uint4 hi, lo;
            tf32_split(v.x, hi.x, lo.x);
            tf32_split(v.y, hi.y, lo.y);
            tf32_split(v.z, hi.z, lo.z);
            tf32_split(v.w, hi.w, lo.w);
            *(uint4*)&AsH[r][q*4] = hi;
            *(uint4*)&AsL[r][q*4] = lo;
        }
        // --- load + pre-split B tile: 32 k x 64 cols ---
        #pragma unroll
        for (int i = 0; i < 2; i++) {
            int idx = tid + i * 256;
            int kk = idx >> 4;
            int q = idx & 15;
            int c = col0 + q * 4;
            float4 v = make_float4(0.f, 0.f, 0.f, 0.f);
            if ((C & 63) == 0 || c < C)
                v = *(const float4*)(Bw + (k0 + kk) * C + c);
            uint4 hi, lo;
            tf32_split(v.x, hi.x, lo.x);
            tf32_split(v.y, hi.y, lo.y);
            tf32_split(v.z, hi.z, lo.z);
            tf32_split(v.w, hi.w, lo.w);
            *(uint4*)&BsH[kk][q*4] = hi;
            *(uint4*)&BsL[kk][q*4] = lo;
        }
        __syncthreads();

        #pragma unroll
        for (int kk = 0; kk < 4; kk++) {
            uint32_t ahi[2][4], alo[2][4];
            #pragma unroll
            for (int mt = 0; mt < 2; mt++) {
                int r = warp_m * 32 + mt * 16 + g;
                int kc = kk * 8 + t4;
                ahi[mt][0] = AsH[r][kc];     alo[mt][0] = AsL[r][kc];
                ahi[mt][1] = AsH[r+8][kc];   alo[mt][1] = AsL[r+8][kc];
                ahi[mt][2] = AsH[r][kc+4];   alo[mt][2] = AsL[r][kc+4];
                ahi[mt][3] = AsH[r+8][kc+4]; alo[mt][3] = AsL[r+8][kc+4];
            }
            uint32_t bhi[4][2], blo[4][2];
            #pragma unroll
            for (int nt = 0; nt < 4; nt++) {
                int nb = warp_n * 32 + nt * 8 + g;
                int kr = kk * 8 + t4;
                bhi[nt][0] = BsH[kr][nb];    blo[nt][0] = BsL[kr][nb];
                bhi[nt][1] = BsH[kr+4][nb];  blo[nt][1] = BsL[kr+4][nb];
            }
            #pragma unroll
            for (int mt = 0; mt < 2; mt++)
                #pragma unroll
                for (int nt = 0; nt < 4; nt++) {
                    mma_tf32(acc[mt][nt], ahi[mt], bhi[nt]);
                    mma_tf32(acc[mt][nt], ahi[mt], blo[nt]);
                    mma_tf32(acc[mt][nt], alo[mt], bhi[nt]);
                }
        }
        __syncthreads();
    }

    #pragma unroll
    for (int mt = 0; mt < 2; mt++) {
        long rowa = row0 + warp_m * 32 + mt * 16 + g;
        long rowb = rowa + 8;
        #pragma unroll
        for (int nt = 0; nt < 4; nt++) {
            int col = col0 + warp_n * 32 + nt * 8 + 2 * t4;
            if ((C & 63) == 0 || col < C) {
                float bx = bias[col];
                float by = bias[col + 1];
                float* d0 = Cout + rowa * C + col;
                float* d1 = Cout + rowb * C + col;
                float2 v0 = make_float2(acc[mt][nt][0] + bx, acc[mt][nt][1] + by);
                float2 v1 = make_float2(acc[mt][nt][2] + bx, acc[mt][nt][3] + by);
                if (ACCUM) {
                    float2 o0 = *(const float2*)d0;
                    float2 o1 = *(const float2*)d1;
                    v0.x += o0.x; v0.y += o0.y;
                    v1.x += o1.x; v1.y += o1.y;
                }
                *(float2*)d0 = v0;
                *(float2*)d1 = v1;
            }
        }
    }
}

// ---------------- SpMM (s = a_hat @ t per graph) + BN stats partials ----------------
// Round-4 layout (known good): blockDim (16,16), x*4 = channel float4, y = row lane.
// Unroll-4 gathers, dual accumulators, packed (col,val) stream.
__global__ __launch_bounds__(256) void spmm_stats(
    const float* __restrict__ T, float* __restrict__ S)
{
    int g = blockIdx.y;
    int m0 = blockIdx.x * 125;
    int cx = threadIdx.x;
    int c4 = cx * 4;
    int yr = threadIdx.y;
    const float* tg = T + (long)g * NN * HID;
    float* sg = S + (long)g * NN * HID;
    float lsum[4] = {0,0,0,0}, lsq[4] = {0,0,0,0};

    for (int m = m0 + yr; m < m0 + 125; m += 16) {
        int jb = g_rowptr[m], je = g_rowptr[m + 1];
        float4 a0 = make_float4(0.f, 0.f, 0.f, 0.f);
        float4 a1 = make_float4(0.f, 0.f, 0.f, 0.f);
        int j = jb;
        for (; j + 3 < je; j += 4) {
            float2 cv0 = g_ecsr[j],     cv1 = g_ecsr[j + 1];
            float2 cv2 = g_ecsr[j + 2], cv3 = g_ecsr[j + 3];
            int   c0 = __float_as_int(cv0.x), c1 = __float_as_int(cv1.x);
            int   c2 = __float_as_int(cv2.x), c3 = __float_as_int(cv3.x);
            float w0 = cv0.y, w1 = cv1.y, w2 = cv2.y, w3 = cv3.y;
            float4 t0 = *(const float4*)(tg + c0 * HID + c4);
            float4 t1 = *(const float4*)(tg + c1 * HID + c4);
            float4 t2 = *(const float4*)(tg + c2 * HID + c4);
            float4 t3 = *(const float4*)(tg + c3 * HID + c4);
            a0.x += w0 * t0.x + w1 * t1.x;  a1.x += w2 * t2.x + w3 * t3.x;
            a0.y += w0 * t0.y + w1 * t1.y;  a1.y += w2 * t2.y + w3 * t3.y;
            a0.z += w0 * t0.z + w1 * t1.z;  a1.z += w2 * t2.z + w3 * t3.z;
            a0.w += w0 * t0.w + w1 * t1.w;  a1.w += w2 * t2.w + w3 * t3.w;
        }
        for (; j < je; j++) {
            float2 cv = g_ecsr[j];
            int col = __float_as_int(cv.x);
            float w = cv.y;
            float4 tv = *(const float4*)(tg + col * HID + c4);
            a0.x += w * tv.x; a0.y += w * tv.y;
            a0.z += w * tv.z; a0.w += w * tv.w;
        }
        float4 acc = make_float4(a0.x + a1.x, a0.y + a1.y, a0.z + a1.z, a0.w + a1.w);
        *(float4*)(sg + m * HID + c4) = acc;
        lsum[0] += acc.x; lsum[1] += acc.y; lsum[2] += acc.z; lsum[3] += acc.w;
        lsq[0] += acc.x * acc.x; lsq[1] += acc.y * acc.y;
        lsq[2] += acc.z * acc.z; lsq[3] += acc.w * acc.w;
    }

    __shared__ float red[16][64];
    #pragma unroll
    for (int k = 0; k < 4; k++) red[yr][c4 + k] = lsum[k];
    __syncthreads();
    for (int off = 8; off >= 1; off >>= 1) {
        if (yr < off)
            #pragma unroll
            for (int k = 0; k < 4; k++) red[yr][c4 + k] += red[yr + off][c4 + k];
        __syncthreads();
    }
    if (yr == 0)
        #pragma unroll
        for (int k = 0; k < 4; k++) atomicAdd(&g_sum[c4 + k], red[0][c4 + k]);
    __syncthreads();
    #pragma unroll
    for (int k = 0; k < 4; k++) red[yr][c4 + k] = lsq[k];
    __syncthreads();
    for (int off = 8; off >= 1; off >>= 1) {
        if (yr < off)
            #pragma unroll
            for (int k = 0; k < 4; k++) red[yr][c4 + k] += red[yr + off][c4 + k];
        __syncthreads();
    }
    if (yr == 0)
        #pragma unroll
        for (int k = 0; k < 4; k++) atomicAdd(&g_sumsq[c4 + k], red[0][c4 + k]);
}

// ---------------- BN finalize ----------------
__global__ void bn_finalize(const float* __restrict__ gamma, const float* __restrict__ beta) {
    int c = threadIdx.x;
    float s = g_sum[c], q = g_sumsq[c];
    const float inv = 1.f / (float)ROWS;
    float mean = s * inv;
    float var = q * inv - mean * mean;
    float rstd = rsqrtf(var + BN_EPS);
    float a = rstd * gamma[c];
    g_scale[c] = a;
    g_shift[c] = beta[c] - mean * a;
    g_sum[c] = 0.f; g_sumsq[c] = 0.f;
}

// ---------------- launch ----------------
extern "C" void kernel_launch(void* const* d_in, const int* in_sizes, int n_in,
                              void* d_out, int out_size)
{
    const float* x     = (const float*)d_in[0];
    const float* adj   = (const float*)d_in[1];
    const float* w_g0  = (const float*)d_in[2];
    const float* b_g0  = (const float*)d_in[3];
    const float* w_g1  = (const float*)d_in[4];
    const float* b_g1  = (const float*)d_in[5];
    const float* w_g2  = (const float*)d_in[6];
    const float* b_g2  = (const float*)d_in[7];
    const float* gamma = (const float*)d_in[8];
    const float* beta  = (const float*)d_in[9];
    const float* w_r0  = (const float*)d_in[10];
    const float* b_r0  = (const float*)d_in[11];
    const float* w_fc  = (const float*)d_in[12];
    const float* b_fc  = (const float*)d_in[13];
    const float* w_fr  = (const float*)d_in[14];
    const float* b_fr  = (const float*)d_in[15];
    float* out = (float*)d_out;

    float *pt, *ps, *ph, *pr;
    cudaGetSymbolAddress((void**)&pt, g_t);
    cudaGetSymbolAddress((void**)&ps, g_s);
    cudaGetSymbolAddress((void**)&ph, g_h);
    cudaGetSymbolAddress((void**)&pr, g_r);

    const int ROWB = ROWS / 128;               // 2000

    // allow >48KB dynamic smem on all gemm instantiations
    cudaFuncSetAttribute(gemm_tc<FIN, HID, false, false, false>,
                         cudaFuncAttributeMaxDynamicSharedMemorySize, GEMM_SMEM_BYTES);
    cudaFuncSetAttribute(gemm_tc<FIN, OUTF, false, false, false>,
                         cudaFuncAttributeMaxDynamicSharedMemorySize, GEMM_SMEM_BYTES);
    cudaFuncSetAttribute(gemm_tc<HID, HID, false, true, true>,
                         cudaFuncAttributeMaxDynamicSharedMemorySize, GEMM_SMEM_BYTES);
    cudaFuncSetAttribute(gemm_tc<HID, OUTF, true, true, false>,
                         cudaFuncAttributeMaxDynamicSharedMemorySize, GEMM_SMEM_BYTES);

    // CSR of a_hat (recomputed every launch; tiny, fully deterministic)
    prep_deg<<<NN, 128>>>(adj);
    prep_scan<<<1, 512>>>();
    prep_fill<<<4, 128>>>(adj);

    // input GEMMs: t0 = x@w_g0+b, r0 = x@w_r0+b, out = x@w_fr+b_fr
    gemm_tc<FIN, HID, false, false, false><<<dim3(ROWB, 1), 256, GEMM_SMEM_BYTES>>>(x, nullptr, nullptr, w_g0, b_g0, pt);
    gemm_tc<FIN, HID, false, false, false><<<dim3(ROWB, 1), 256, GEMM_SMEM_BYTES>>>(x, nullptr, nullptr, w_r0, b_r0, pr);
    gemm_tc<FIN, OUTF, false, false, false><<<dim3(ROWB, 2), 256, GEMM_SMEM_BYTES>>>(x, nullptr, nullptr, w_fr, b_fr, out);

    // layer 0: s = a_hat @ t0; h0 = relu(bn(s)) + r0; t1 = h0 @ w_g1 + b
    spmm_stats<<<dim3(4, GG), dim3(16, 16)>>>(pt, ps);
    bn_finalize<<<1, HID>>>(gamma + 0 * HID, beta + 0 * HID);
    gemm_tc<HID, HID, false, true, true><<<dim3(ROWB, 1), 256, GEMM_SMEM_BYTES>>>(ps, pr, ph, w_g1, b_g1, pt);

    // layer 1: s = a_hat @ t1; h1 = relu(bn(s)) + h0; t2 = h1 @ w_g2 + b
    spmm_stats<<<dim3(4, GG), dim3(16, 16)>>>(pt, ps);
    bn_finalize<<<1, HID>>>(gamma + 1 * HID, beta + 1 * HID);
    gemm_tc<HID, HID, false, true, true><<<dim3(ROWB, 1), 256, GEMM_SMEM_BYTES>>>(ps, ph, ph, w_g2, b_g2, pt);

    // layer 2: s = a_hat @ t2; h2 = relu(bn(s)) + h1 (never materialized);
    //          out += h2 @ w_fc + b_fc
    spmm_stats<<<dim3(4, GG), dim3(16, 16)>>>(pt, ps);
    bn_finalize<<<1, HID>>>(gamma + 2 * HID, beta + 2 * HID);
    gemm_tc<HID, OUTF, true, true, false><<<dim3(ROWB, 2), 256, GEMM_SMEM_BYTES>>>(ps, ph, nullptr, w_fc, b_fc, out);
}

// round 7
// speedup vs baseline: 1.1914x; 1.0447x over previous
#include <cuda_runtime.h>
#include <cuda_fp16.h>
#include <cstdint>

#define GG 512            // B*T graphs
#define NN 500            // nodes
#define FIN 96
#define HID 64
#define OUTF 96
#define ROWS (GG*NN)      // 256000
#define BN_EPS 1e-5f
#define NNZ_MAX (NN*NN)

// ---------------- scratch (device globals; no allocation allowed) ----------------
__device__ __half2 g_t16[(long)ROWS*HID/2]; // GEMM output / SpMM input (fp16!)
__device__ float g_s[(long)ROWS*HID];    // SpMM output
__device__ float g_h[(long)ROWS*HID];    // layer activations (residual chain)
__device__ float g_r[(long)ROWS*HID];    // layer-0 residual (x @ w_r0 + b_r0)
__device__ float g_dinv[NN];
__device__ int   g_cnt[NN];
__device__ int   g_rowptr[NN+1];
__device__ float2 g_ecsr[NNZ_MAX];       // packed (col-as-int-bits, val)
__device__ float g_sum[HID];
__device__ float g_sumsq[HID];
__device__ float g_scale[HID];
__device__ float g_shift[HID];

// ---------------- prep: degrees / dinv + per-row nnz counts ----------------
__global__ void prep_deg(const float* __restrict__ adj) {
    int m = blockIdx.x;
    int tid = threadIdx.x;
    float sum = 0.f; int cnt = 0;
    for (int n = tid; n < NN; n += blockDim.x) {
        float a = adj[m*NN + n];
        sum += a;
        cnt += (a != 0.f) ? 1 : 0;
    }
    __shared__ float ssum[4]; __shared__ int scnt[4];
    #pragma unroll
    for (int o = 16; o; o >>= 1) {
        sum += __shfl_down_sync(0xFFFFFFFFu, sum, o);
        cnt += __shfl_down_sync(0xFFFFFFFFu, cnt, o);
    }
    int w = tid >> 5;
    if ((tid & 31) == 0) { ssum[w] = sum; scnt[w] = cnt; }
    __syncthreads();
    if (tid == 0) {
        float s = ssum[0] + ssum[1] + ssum[2] + ssum[3];
        int c = scnt[0] + scnt[1] + scnt[2] + scnt[3];
        g_dinv[m] = rsqrtf(1.f + s);
        g_cnt[m] = c + 1;   // + diagonal
    }
    if (blockIdx.x == 0 && tid < HID) { g_sum[tid] = 0.f; g_sumsq[tid] = 0.f; }
}

// exclusive scan of row counts -> rowptr (single block)
__global__ void prep_scan() {
    __shared__ int sc[512];
    int tid = threadIdx.x;
    sc[tid] = (tid < NN) ? g_cnt[tid] : 0;
    __syncthreads();
    for (int off = 1; off < 512; off <<= 1) {
        int v = (tid >= off) ? sc[tid - off] : 0;
        __syncthreads();
        sc[tid] += v;
        __syncthreads();
    }
    if (tid < NN) g_rowptr[tid + 1] = sc[tid];
    if (tid == 0) g_rowptr[0] = 0;
}

// fill CSR with normalized values (deterministic: one thread per row, ascending cols)
__global__ void prep_fill(const float* __restrict__ adj) {
    int m = blockIdx.x * blockDim.x + threadIdx.x;
    if (m >= NN) return;
    float dm = g_dinv[m];
    int p = g_rowptr[m];
    for (int n = 0; n < NN; n++) {
        if (n == m) {
            g_ecsr[p] = make_float2(__int_as_float(m), dm * dm);
            p++;
        } else {
            float a = adj[m*NN + n];
            if (a != 0.f) {
                g_ecsr[p] = make_float2(__int_as_float(n), dm * a * g_dinv[n]);
                p++;
            }
        }
    }
}

// ---------------- tensor-core GEMM (3xTF32 split, fp32-equivalent accuracy) -------
// C[row,c] = sum_f A'[row,f]*B[f,c] + bias[c]   (optional += existing C)
// FUSE: A'[row,f] = max(A[row,f]*scale[f]+shift[f], 0) + R[row,f]  (BN+ReLU+residual)
//       optionally written out to Hout.
// OUT_HALF: result stored as __half2 (t feeding the SpMM gather path).
// hi/lo tf32 planes are PRE-SPLIT into smem at tile-load time.

__device__ __forceinline__ void tf32_split(float x, uint32_t& hi, uint32_t& lo) {
    asm("cvt.rna.tf32.f32 %0, %1;" : "=r"(hi) : "f"(x));
    float r = x - __uint_as_float(hi);
    asm("cvt.rna.tf32.f32 %0, %1;" : "=r"(lo) : "f"(r));
}

__device__ __forceinline__ void mma_tf32(float* c, const uint32_t* a, const uint32_t* b) {
    asm volatile(
        "mma.sync.aligned.m16n8k8.row.col.f32.tf32.tf32.f32 "
        "{%0,%1,%2,%3}, {%4,%5,%6,%7}, {%8,%9}, {%0,%1,%2,%3};\n"
        : "+f"(c[0]), "+f"(c[1]), "+f"(c[2]), "+f"(c[3])
        : "r"(a[0]), "r"(a[1]), "r"(a[2]), "r"(a[3]), "r"(b[0]), "r"(b[1]));
}

// dynamic smem layout (uint32 words):
//   AsH [128][36] | AsL [128][36] | BsH [32][72] | BsL [32][72]
#define GEMM_SMEM_WORDS (4608*2 + 2304*2)
#define GEMM_SMEM_BYTES (GEMM_SMEM_WORDS * 4)

template<int K, int C, bool ACCUM, bool FUSE, bool WRITE_H, bool OUT_HALF>
__global__ __launch_bounds__(256) void gemm_tc(
    const float* __restrict__ A, const float* __restrict__ R, float* __restrict__ Hout,
    const float* __restrict__ Bw, const float* __restrict__ bias, void* __restrict__ Cout)
{
    extern __shared__ uint32_t dsm[];
    uint32_t (*AsH)[36] = (uint32_t(*)[36])(dsm);
    uint32_t (*AsL)[36] = (uint32_t(*)[36])(dsm + 4608);
    uint32_t (*BsH)[72] = (uint32_t(*)[72])(dsm + 9216);
    uint32_t (*BsL)[72] = (uint32_t(*)[72])(dsm + 11520);
    __shared__ float s_scale[HID], s_shift[HID];

    const int tid = threadIdx.x;
    const int wid = tid >> 5;
    const int lane = tid & 31;
    const int g  = lane >> 2;
    const int t4 = lane & 3;
    const int warp_m = wid >> 1;
    const int warp_n = wid & 1;

    const long row0 = (long)blockIdx.x * 128;
    const int col0 = blockIdx.y * 64;

    if (FUSE) {
        if (tid < HID) s_scale[tid] = g_scale[tid];
        else if (tid < 2*HID) s_shift[tid - HID] = g_shift[tid - HID];
        __syncthreads();
    }

    float acc[2][4][4];
    #pragma unroll
    for (int mt = 0; mt < 2; mt++)
        #pragma unroll
        for (int nt = 0; nt < 4; nt++)
            #pragma unroll
            for (int q = 0; q < 4; q++) acc[mt][nt][q] = 0.f;

    for (int k0 = 0; k0 < K; k0 += 32) {
        #pragma unroll
        for (int i = 0; i < 4; i++) {
            int idx = tid + i * 256;
            int r = idx >> 3;
            int q = idx & 7;
            long off = (row0 + r) * K + (k0 + q * 4);
            float4 v = *(const float4*)(A + off);
            if (FUSE) {
                int kc = k0 + q * 4;
                float4 rv = *(const float4*)(R + off);
                v.x = fmaxf(v.x * s_scale[kc+0] + s_shift[kc+0], 0.f) + rv.x;
                v.y = fmaxf(v.y * s_scale[kc+1] + s_shift[kc+1], 0.f) + rv.y;
                v.z = fmaxf(v.z * s_scale[kc+2] + s_shift[kc+2], 0.f) + rv.z;
                v.w = fmaxf(v.w * s_scale[kc+3] + s_shift[kc+3], 0.f) + rv.w;
                if (WRITE_H) *(float4*)(Hout + off) = v;
            }
            uint4 hi, lo;
            tf32_split(v.x, hi.x, lo.x);
            tf32_split(v.y, hi.y, lo.y);
            tf32_split(v.z, hi.z, lo.z);
            tf32_split(v.w, hi.w, lo.w);
            *(uint4*)&AsH[r][q*4] = hi;
            *(uint4*)&AsL[r][q*4] = lo;
        }
        #pragma unroll
        for (int i = 0; i < 2; i++) {
            int idx = tid + i * 256;
            int kk = idx >> 4;
            int q = idx & 15;
            int c = col0 + q * 4;
            float4 v = make_float4(0.f, 0.f, 0.f, 0.f);
            if ((C & 63) == 0 || c < C)
                v = *(const float4*)(Bw + (k0 + kk) * C + c);
            uint4 hi, lo;
            tf32_split(v.x, hi.x, lo.x);
            tf32_split(v.y, hi.y, lo.y);
            tf32_split(v.z, hi.z, lo.z);
            tf32_split(v.w, hi.w, lo.w);
            *(uint4*)&BsH[kk][q*4] = hi;
            *(uint4*)&BsL[kk][q*4] = lo;
        }
        __syncthreads();

        #pragma unroll
        for (int kk = 0; kk < 4; kk++) {
            uint32_t ahi[2][4], alo[2][4];
            #pragma unroll
            for (int mt = 0; mt < 2; mt++) {
                int r = warp_m * 32 + mt * 16 + g;
                int kc = kk * 8 + t4;
                ahi[mt][0] = AsH[r][kc];     alo[mt][0] = AsL[r][kc];
                ahi[mt][1] = AsH[r+8][kc];   alo[mt][1] = AsL[r+8][kc];
                ahi[mt][2] = AsH[r][kc+4];   alo[mt][2] = AsL[r][kc+4];
                ahi[mt][3] = AsH[r+8][kc+4]; alo[mt][3] = AsL[r+8][kc+4];
            }
            uint32_t bhi[4][2], blo[4][2];
            #pragma unroll
            for (int nt = 0; nt < 4; nt++) {
                int nb = warp_n * 32 + nt * 8 + g;
                int kr = kk * 8 + t4;
                bhi[nt][0] = BsH[kr][nb];    blo[nt][0] = BsL[kr][nb];
                bhi[nt][1] = BsH[kr+4][nb];  blo[nt][1] = BsL[kr+4][nb];
            }
            #pragma unroll
            for (int mt = 0; mt < 2; mt++)
                #pragma unroll
                for (int nt = 0; nt < 4; nt++) {
                    mma_tf32(acc[mt][nt], ahi[mt], bhi[nt]);
                    mma_tf32(acc[mt][nt], ahi[mt], blo[nt]);
                    mma_tf32(acc[mt][nt], alo[mt], bhi[nt]);
                }
        }
        __syncthreads();
    }

    #pragma unroll
    for (int mt = 0; mt < 2; mt++) {
        long rowa = row0 + warp_m * 32 + mt * 16 + g;
        long rowb = rowa + 8;
        #pragma unroll
        for (int nt = 0; nt < 4; nt++) {
            int col = col0 + warp_n * 32 + nt * 8 + 2 * t4;
            if ((C & 63) == 0 || col < C) {
                float bx = bias[col];
                float by = bias[col + 1];
                float2 v0 = make_float2(acc[mt][nt][0] + bx, acc[mt][nt][1] + by);
                float2 v1 = make_float2(acc[mt][nt][2] + bx, acc[mt][nt][3] + by);
                if (OUT_HALF) {
                    __half2* o = (__half2*)Cout;
                    o[(rowa * C + col) >> 1] = __floats2half2_rn(v0.x, v0.y);
                    o[(rowb * C + col) >> 1] = __floats2half2_rn(v1.x, v1.y);
                } else {
                    float* d0 = (float*)Cout + rowa * C + col;
                    float* d1 = (float*)Cout + rowb * C + col;
                    if (ACCUM) {
                        float2 o0 = *(const float2*)d0;
                        float2 o1 = *(const float2*)d1;
                        v0.x += o0.x; v0.y += o0.y;
                        v1.x += o1.x; v1.y += o1.y;
                    }
                    *(float2*)d0 = v0;
                    *(float2*)d1 = v1;
                }
            }
        }
    }
}

// ---------------- SpMM (s = a_hat @ t per graph) + BN stats partials ----------------
// blockDim (16,16), x = channel quad (4 ch), y = row lane. T is fp16 (__half2):
// one T row = 64 ch = 128 B = ONE cache line per gather (was two).
// Unroll-4 gathers, dual fp32 accumulators, packed (col,val) stream.
__global__ __launch_bounds__(256) void spmm_stats(
    const __half2* __restrict__ T2, float* __restrict__ S)
{
    int g = blockIdx.y;
    int m0 = blockIdx.x * 125;
    int cx = threadIdx.x;
    int c4 = cx * 4;
    int yr = threadIdx.y;
    const __half2* tg = T2 + (long)g * NN * (HID/2);
    float* sg = S + (long)g * NN * HID;
    float lsum[4] = {0,0,0,0}, lsq[4] = {0,0,0,0};

    for (int m = m0 + yr; m < m0 + 125; m += 16) {
        int jb = g_rowptr[m], je = g_rowptr[m + 1];
        float4 a0 = make_float4(0.f, 0.f, 0.f, 0.f);
        float4 a1 = make_float4(0.f, 0.f, 0.f, 0.f);
        int j = jb;
        for (; j + 3 < je; j += 4) {
            float2 cv0 = g_ecsr[j],     cv1 = g_ecsr[j + 1];
            float2 cv2 = g_ecsr[j + 2], cv3 = g_ecsr[j + 3];
            int   c0 = __float_as_int(cv0.x), c1 = __float_as_int(cv1.x);
            int   c2 = __float_as_int(cv2.x), c3 = __float_as_int(cv3.x);
            float w0 = cv0.y, w1 = cv1.y, w2 = cv2.y, w3 = cv3.y;
            // 8B per thread, half-warp covers one 128B line
            uint2 r0 = *(const uint2*)(tg + c0 * (HID/2) + cx * 2);
            uint2 r1 = *(const uint2*)(tg + c1 * (HID/2) + cx * 2);
            uint2 r2 = *(const uint2*)(tg + c2 * (HID/2) + cx * 2);
            uint2 r3 = *(const uint2*)(tg + c3 * (HID/2) + cx * 2);
            float2 t0a = __half22float2(*(__half2*)&r0.x), t0b = __half22float2(*(__half2*)&r0.y);
            float2 t1a = __half22float2(*(__half2*)&r1.x), t1b = __half22float2(*(__half2*)&r1.y);
            float2 t2a = __half22float2(*(__half2*)&r2.x), t2b = __half22float2(*(__half2*)&r2.y);
            float2 t3a = __half22float2(*(__half2*)&r3.x), t3b = __half22float2(*(__half2*)&r3.y);
            a0.x += w0 * t0a.x + w1 * t1a.x;  a1.x += w2 * t2a.x + w3 * t3a.x;
            a0.y += w0 * t0a.y + w1 * t1a.y;  a1.y += w2 * t2a.y + w3 * t3a.y;
            a0.z += w0 * t0b.x + w1 * t1b.x;  a1.z += w2 * t2b.x + w3 * t3b.x;
            a0.w += w0 * t0b.y + w1 * t1b.y;  a1.w += w2 * t2b.y + w3 * t3b.y;
        }
        for (; j < je; j++) {
            float2 cv = g_ecsr[j];
            int col = __float_as_int(cv.x);
            float w = cv.y;
            uint2 r = *(const uint2*)(tg + col * (HID/2) + cx * 2);
            float2 ta = __half22float2(*(__half2*)&r.x), tb = __half22float2(*(__half2*)&r.y);
            a0.x += w * ta.x; a0.y += w * ta.y;
            a0.z += w * tb.x; a0.w += w * tb.y;
        }
        float4 acc = make_float4(a0.x + a1.x, a0.y + a1.y, a0.z + a1.z, a0.w + a1.w);
        *(float4*)(sg + m * HID + c4) = acc;
        lsum[0] += acc.x; lsum[1] += acc.y; lsum[2] += acc.z; lsum[3] += acc.w;
        lsq[0] += acc.x * acc.x; lsq[1] += acc.y * acc.y;
        lsq[2] += acc.z * acc.z; lsq[3] += acc.w * acc.w;
    }

    __shared__ float red[16][64];
    #pragma unroll
    for (int k = 0; k < 4; k++) red[yr][c4 + k] = lsum[k];
    __syncthreads();
    for (int off = 8; off >= 1; off >>= 1) {
        if (yr < off)
            #pragma unroll
            for (int k = 0; k < 4; k++) red[yr][c4 + k] += red[yr + off][c4 + k];
        __syncthreads();
    }
    if (yr == 0)
        #pragma unroll
        for (int k = 0; k < 4; k++) atomicAdd(&g_sum[c4 + k], red[0][c4 + k]);
    __syncthreads();
    #pragma unroll
    for (int k = 0; k < 4; k++) red[yr][c4 + k] = lsq[k];
    __syncthreads();
    for (int off = 8; off >= 1; off >>= 1) {
        if (yr < off)
            #pragma unroll
            for (int k = 0; k < 4; k++) red[yr][c4 + k] += red[yr + off][c4 + k];
        __syncthreads();
    }
    if (yr == 0)
        #pragma unroll
        for (int k = 0; k < 4; k++) atomicAdd(&g_sumsq[c4 + k], red[0][c4 + k]);
}

// ---------------- BN finalize ----------------
__global__ void bn_finalize(const float* __restrict__ gamma, const float* __restrict__ beta) {
    int c = threadIdx.x;
    float s = g_sum[c], q = g_sumsq[c];
    const float inv = 1.f / (float)ROWS;
    float mean = s * inv;
    float var = q * inv - mean * mean;
    float rstd = rsqrtf(var + BN_EPS);
    float a = rstd * gamma[c];
    g_scale[c] = a;
    g_shift[c] = beta[c] - mean * a;
    g_sum[c] = 0.f; g_sumsq[c] = 0.f;
}

// ---------------- launch ----------------
extern "C" void kernel_launch(void* const* d_in, const int* in_sizes, int n_in,
                              void* d_out, int out_size)
{
    const float* x     = (const float*)d_in[0];
    const float* adj   = (const float*)d_in[1];
    const float* w_g0  = (const float*)d_in[2];
    const float* b_g0  = (const float*)d_in[3];
    const float* w_g1  = (const float*)d_in[4];
    const float* b_g1  = (const float*)d_in[5];
    const float* w_g2  = (const float*)d_in[6];
    const float* b_g2  = (const float*)d_in[7];
    const float* gamma = (const float*)d_in[8];
    const float* beta  = (const float*)d_in[9];
    const float* w_r0  = (const float*)d_in[10];
    const float* b_r0  = (const float*)d_in[11];
    const float* w_fc  = (const float*)d_in[12];
    const float* b_fc  = (const float*)d_in[13];
    const float* w_fr  = (const float*)d_in[14];
    const float* b_fr  = (const float*)d_in[15];
    float* out = (float*)d_out;

    __half2 *pt16;
    float *ps, *ph, *pr;
    cudaGetSymbolAddress((void**)&pt16, g_t16);
    cudaGetSymbolAddress((void**)&ps, g_s);
    cudaGetSymbolAddress((void**)&ph, g_h);
    cudaGetSymbolAddress((void**)&pr, g_r);

    const int ROWB = ROWS / 128;               // 2000

    cudaFuncSetAttribute(gemm_tc<FIN, HID, false, false, false, true>,
                         cudaFuncAttributeMaxDynamicSharedMemorySize, GEMM_SMEM_BYTES);
    cudaFuncSetAttribute(gemm_tc<FIN, HID, false, false, false, false>,
                         cudaFuncAttributeMaxDynamicSharedMemorySize, GEMM_SMEM_BYTES);
    cudaFuncSetAttribute(gemm_tc<FIN, OUTF, false, false, false, false>,
                         cudaFuncAttributeMaxDynamicSharedMemorySize, GEMM_SMEM_BYTES);
    cudaFuncSetAttribute(gemm_tc<HID, HID, false, true, true, true>,
                         cudaFuncAttributeMaxDynamicSharedMemorySize, GEMM_SMEM_BYTES);
    cudaFuncSetAttribute(gemm_tc<HID, OUTF, true, true, false, false>,
                         cudaFuncAttributeMaxDynamicSharedMemorySize, GEMM_SMEM_BYTES);

    // CSR of a_hat (recomputed every launch; tiny, fully deterministic)
    prep_deg<<<NN, 128>>>(adj);
    prep_scan<<<1, 512>>>();
    prep_fill<<<4, 128>>>(adj);

    // input GEMMs: t0 = fp16(x@w_g0+b), r0 = x@w_r0+b, out = x@w_fr+b_fr
    gemm_tc<FIN, HID, false, false, false, true><<<dim3(ROWB, 1), 256, GEMM_SMEM_BYTES>>>(x, nullptr, nullptr, w_g0, b_g0, pt16);
    gemm_tc<FIN, HID, false, false, false, false><<<dim3(ROWB, 1), 256, GEMM_SMEM_BYTES>>>(x, nullptr, nullptr, w_r0, b_r0, pr);
    gemm_tc<FIN, OUTF, false, false, false, false><<<dim3(ROWB, 2), 256, GEMM_SMEM_BYTES>>>(x, nullptr, nullptr, w_fr, b_fr, out);

    // layer 0: s = a_hat @ t0; h0 = relu(bn(s)) + r0; t1 = fp16(h0 @ w_g1 + b)
    spmm_stats<<<dim3(4, GG), dim3(16, 16)>>>(pt16, ps);
    bn_finalize<<<1, HID>>>(gamma + 0 * HID, beta + 0 * HID);
    gemm_tc<HID, HID, false, true, true, true><<<dim3(ROWB, 1), 256, GEMM_SMEM_BYTES>>>(ps, pr, ph, w_g1, b_g1, pt16);

    // layer 1: s = a_hat @ t1; h1 = relu(bn(s)) + h0; t2 = fp16(h1 @ w_g2 + b)
    spmm_stats<<<dim3(4, GG), dim3(16, 16)>>>(pt16, ps);
    bn_finalize<<<1, HID>>>(gamma + 1 * HID, beta + 1 * HID);
    gemm_tc<HID, HID, false, true, true, true><<<dim3(ROWB, 1), 256, GEMM_SMEM_BYTES>>>(ps, ph, ph, w_g2, b_g2, pt16);

    // layer 2: s = a_hat @ t2; h2 = relu(bn(s)) + h1 (never materialized);
    //          out += h2 @ w_fc + b_fc
    spmm_stats<<<dim3(4, GG), dim3(16, 16)>>>(pt16, ps);
    bn_finalize<<<1, HID>>>(gamma + 2 * HID, beta + 2 * HID);
    gemm_tc<HID, OUTF, true, true, false, false><<<dim3(ROWB, 2), 256, GEMM_SMEM_BYTES>>>(ps, ph, nullptr, w_fc, b_fc, out);
}